// round 14
// baseline (speedup 1.0000x reference)
#include <cuda_runtime.h>
#include <cuda_fp16.h>
#include <cstdint>

#define Bsz 8192
#define Lsz 16
#define Hsz 512
#define Ssz 64
#define Dsz 16

// ---------------- device scratch ----------------
__device__ int g_perm[Bsz];
__device__ int g_dstart[Dsz + 1];
__device__ int g_tile_d[96];
__device__ int g_tile_r0[96];
__device__ int g_ntiles;

// activations: fp16 hi/lo planes, ping-pong buffers
__device__ __half g_aH[2][Bsz * Hsz];
__device__ __half g_aL[2][Bsz * Hsz];

// weights: single fp16 plane, transposed to [N, K] K-major
__device__ __half g_tW[3][Hsz * Hsz];
__device__ __half g_hW[3][Dsz * Hsz * Hsz];
__device__ __half g_fW[Dsz * Ssz * Hsz];

__device__ __forceinline__ float lrelu(float x) { return x >= 0.0f ? x : 0.2f * x; }

__device__ __forceinline__ uint32_t smem_u32(const void* p) {
    uint32_t a;
    asm("{ .reg .u64 t; cvta.to.shared.u64 t, %1; cvt.u32.u64 %0, t; }" : "=r"(a) : "l"(p));
    return a;
}

__device__ __forceinline__ void cp_async16(uint32_t daddr, const void* gp) {
    asm volatile("cp.async.cg.shared.global [%0], [%1], 16;" :: "r"(daddr), "l"(gp));
}
__device__ __forceinline__ void cp_commit() {
    asm volatile("cp.async.commit_group;" ::: "memory");
}
__device__ __forceinline__ void cp_wait0() {
    asm volatile("cp.async.wait_group 0;" ::: "memory");
}
__device__ __forceinline__ void cp_wait1() {
    asm volatile("cp.async.wait_group 1;" ::: "memory");
}

__device__ __forceinline__ void ldm4(uint32_t& r0, uint32_t& r1, uint32_t& r2, uint32_t& r3,
                                     uint32_t addr) {
    asm volatile("ldmatrix.sync.aligned.m8n8.x4.shared.b16 {%0,%1,%2,%3}, [%4];"
                 : "=r"(r0), "=r"(r1), "=r"(r2), "=r"(r3) : "r"(addr));
}

__device__ __forceinline__ void mma16816(float (&c)[4], const uint32_t (&a)[4],
                                         uint32_t b0, uint32_t b1) {
    asm("mma.sync.aligned.m16n8k16.row.col.f32.f16.f16.f32 "
        "{%0,%1,%2,%3}, {%4,%5,%6,%7}, {%8,%9}, {%0,%1,%2,%3};"
        : "+f"(c[0]), "+f"(c[1]), "+f"(c[2]), "+f"(c[3])
        : "r"(a[0]), "r"(a[1]), "r"(a[2]), "r"(a[3]), "r"(b0), "r"(b1));
}

__device__ __forceinline__ uint32_t hpack(float a, float b) {
    __half ha = __float2half_rn(a), hb = __float2half_rn(b);
    return (uint32_t)__half_as_ushort(ha) | ((uint32_t)__half_as_ushort(hb) << 16);
}

// ---------------- fused bucketing ----------------
__global__ __launch_bounds__(1024) void k_bucket(const int* __restrict__ y) {
    __shared__ int cnt[Dsz];
    __shared__ int off[Dsz];
    int tid = threadIdx.x;
    if (tid < Dsz) cnt[tid] = 0;
    __syncthreads();
    for (int i = tid; i < Bsz; i += 1024) atomicAdd(&cnt[y[i]], 1);
    __syncthreads();
    if (tid == 0) {
        int s = 0;
        int nt = 0;
        for (int d = 0; d < Dsz; ++d) {
            g_dstart[d] = s;
            off[d] = s;
            for (int r = s; r < s + cnt[d]; r += 128) {
                g_tile_d[nt] = d;
                g_tile_r0[nt] = r;
                nt++;
            }
            s += cnt[d];
        }
        g_dstart[Dsz] = s;
        g_ntiles = nt;
    }
    __syncthreads();
    for (int i = tid; i < Bsz; i += 1024) {
        int p = atomicAdd(&off[y[i]], 1);
        g_perm[p] = i;
    }
}

// ---------------- weight prep: fp32 [K,N] -> fp16 [N,K] ----------------
__global__ void k_prep_all(const float* __restrict__ tW1, const float* __restrict__ tW2,
                           const float* __restrict__ tW3, const float* __restrict__ hW0,
                           const float* __restrict__ hW1, const float* __restrict__ hW2,
                           const float* __restrict__ hW3) {
    __shared__ float t[32][33];
    int gid = blockIdx.x;
    const float* W;
    __half* Th;
    int N, bx, by;
    if (gid < 768) {
        int l = gid >> 8, rem = gid & 255;
        bx = rem & 15; by = rem >> 4;
        W = (l == 0) ? tW1 : (l == 1) ? tW2 : tW3;
        N = Hsz;
        Th = g_tW[l];
    } else if (gid < 13056) {
        int q = gid - 768;
        int l = q / 4096;
        int q2 = q & 4095;
        int z = q2 >> 8, rem = q2 & 255;
        bx = rem & 15; by = rem >> 4;
        const float* base = (l == 0) ? hW0 : (l == 1) ? hW1 : hW2;
        W = base + (size_t)z * Hsz * Hsz;
        N = Hsz;
        Th = g_hW[l] + (size_t)z * Hsz * Hsz;
    } else {
        int q = gid - 13056;
        int z = q >> 5, rem = q & 31;
        bx = rem & 1; by = rem >> 1;
        W = hW3 + (size_t)z * Hsz * Ssz;
        N = Ssz;
        Th = g_fW + (size_t)z * Ssz * Hsz;
    }
    int n0 = bx * 32, k0 = by * 32;
    int tx = threadIdx.x, ty = threadIdx.y;
#pragma unroll
    for (int i = 0; i < 4; ++i)
        t[ty + 8 * i][tx] = W[(size_t)(k0 + ty + 8 * i) * N + n0 + tx];
    __syncthreads();
#pragma unroll
    for (int i = 0; i < 4; ++i) {
        float v = t[tx][ty + 8 * i];
        int n = n0 + ty + 8 * i, k = k0 + tx;
        Th[(size_t)n * Hsz + k] = __float2half_rn(v);
    }
}

// ---------------- layer 0 ----------------
__global__ __launch_bounds__(256) void k_layer0(const float* __restrict__ z,
                                                const float* __restrict__ W,
                                                const float* __restrict__ bias) {
    __shared__ float sW[Lsz * Hsz];
    __shared__ float sb[Hsz];
    int tid = threadIdx.x;
    for (int i = tid; i < Lsz * Hsz; i += 256) sW[i] = W[i];
    for (int i = tid; i < Hsz; i += 256) sb[i] = bias[i];
    __syncthreads();

    int w = tid >> 5, lane = tid & 31;
    for (int q = 0; q < 4; ++q) {
        int p = blockIdx.x * 32 + w * 4 + q;
        int b = g_perm[p];
        float zr[Lsz];
#pragma unroll
        for (int k = 0; k < Lsz; ++k) zr[k] = __ldg(&z[b * Lsz + k]);
#pragma unroll
        for (int it = 0; it < 8; ++it) {
            int c = it * 64 + lane * 2;
            float a0 = sb[c], a1 = sb[c + 1];
#pragma unroll
            for (int k = 0; k < Lsz; ++k) {
                a0 = fmaf(zr[k], sW[k * Hsz + c], a0);
                a1 = fmaf(zr[k], sW[k * Hsz + c + 1], a1);
            }
            a0 = lrelu(a0); a1 = lrelu(a1);
            __half h0 = __float2half_rn(a0), h1 = __float2half_rn(a1);
            float l0 = a0 - __half2float(h0), l1 = a1 - __half2float(h1);
            size_t o = (size_t)p * Hsz + c;
            *(uint32_t*)(&g_aH[0][o]) = (uint32_t)__half_as_ushort(h0) |
                                        ((uint32_t)__half_as_ushort(h1) << 16);
            *(uint32_t*)(&g_aL[0][o]) = hpack(l0, l1);
        }
    }
}

// ---------------- fragment-load helpers ----------------
__device__ __forceinline__ void load_b4(uint32_t (&dst)[4][2], uint32_t base, int jj,
                                        int row0, int row1, int kb) {
    uint32_t r0, r1, r2, r3;
    uint32_t a0 = base + row0 * 128 + (((jj * 2 + kb) ^ (row0 & 7)) << 4);
    ldm4(r0, r1, r2, r3, a0);
    dst[0][0] = r0; dst[0][1] = r2; dst[1][0] = r1; dst[1][1] = r3;
    uint32_t a1 = base + row1 * 128 + (((jj * 2 + kb) ^ (row1 & 7)) << 4);
    ldm4(r0, r1, r2, r3, a1);
    dst[2][0] = r0; dst[2][1] = r2; dst[3][0] = r1; dst[3][1] = r3;
}

__device__ __forceinline__ void load_a2(uint32_t (&dst)[2][4], uint32_t base, int jj,
                                        int row0, int row1, int kb) {
    uint32_t a0 = base + row0 * 128 + (((jj * 2 + kb) ^ (row0 & 7)) << 4);
    ldm4(dst[0][0], dst[0][1], dst[0][2], dst[0][3], a0);
    uint32_t a1 = base + row1 * 128 + (((jj * 2 + kb) ^ (row1 & 7)) << 4);
    ldm4(dst[1][0], dst[1][1], dst[1][2], dst[1][3], a1);
}

__device__ __forceinline__ void mma_2x4(float (&acc)[2][4][4], const uint32_t (&aa)[2][4],
                                        const uint32_t (&bb)[4][2]) {
#pragma unroll
    for (int mi = 0; mi < 2; ++mi)
#pragma unroll
        for (int nj = 0; nj < 4; ++nj)
            mma16816(acc[mi][nj], aa[mi], bb[nj][0], bb[nj][1]);
}

// ---------------- HMMA GEMM: 128x128 tile, 512 threads, fp16x2, 3-stage pipeline ------
// smem: [0,512) bias; A @1024: [3 st][2 pl][16384] = 98304; B @99328: [3 st][16384].
// total 148480 (~145KB) -> 1 CTA/SM, 16 warps, copies get a full chunk of lead time.
#define SM_A_OFF 1024
#define SM_B_OFF 99328
#define SMEM_MAIN 148480

__global__ __launch_bounds__(512) void k_hmma(int src, int dst, int wsel, int lidx,
                                              const float* __restrict__ bias,
                                              int bStride, int headMode) {
    extern __shared__ char sm[];
    int tid = threadIdx.x;
    int t = blockIdx.y;
    int d, rbase, row_hi;
    if (headMode) {
        if (t >= g_ntiles) return;
        d = g_tile_d[t]; rbase = g_tile_r0[t]; row_hi = g_dstart[d + 1];
    } else {
        d = 0; rbase = t * 128; row_hi = Bsz;
    }
    int cb0 = blockIdx.x * 128;
    int rclamp = row_hi - 1;

    const __half* aH = g_aH[src];
    const __half* aL = g_aL[src];
    __half* oH = g_aH[dst];
    __half* oL = g_aL[dst];
    const __half* Wp = (wsel == 0) ? g_tW[lidx]
                                   : (g_hW[lidx] + (size_t)d * Hsz * Hsz);
    Wp += (size_t)cb0 * Hsz;
    const float* bp = bias + (size_t)d * bStride + cb0;

    float* sbias = (float*)sm;
    if (tid < 128) sbias[tid] = bp[tid];
    uint32_t sbase = smem_u32(sm);

    int wid = tid >> 5, lane = tid & 31;
    int wr = wid >> 2, wc = wid & 3;
    int m0 = wr * 32, n0w = wc * 32;
    int kb = lane >> 4;

    int bRow0 = n0w + (lane & 15), bRow1 = n0w + 16 + (lane & 15);
    int aRow0 = m0 + (lane & 15), aRow1 = m0 + 16 + (lane & 15);

    float acc[2][4][4];
#pragma unroll
    for (int i = 0; i < 2; ++i)
#pragma unroll
        for (int j = 0; j < 4; ++j)
#pragma unroll
            for (int k = 0; k < 4; ++k) acc[i][j][k] = 0.0f;

    auto issueA = [&](int kc, int st) {
#pragma unroll
        for (int i = 0; i < 4; ++i) {
            int tt = i * 512 + tid;
            int plane = tt >> 10;
            int row = (tt >> 3) & 127;
            int seg = tt & 7;
            int rg = rbase + row; if (rg > rclamp) rg = rclamp;
            const __half* gp = (plane ? aL : aH) + (size_t)rg * Hsz + kc * 64 + seg * 8;
            uint32_t da = sbase + SM_A_OFF + st * 32768 + plane * 16384 + row * 128 +
                          ((seg ^ (row & 7)) << 4);
            cp_async16(da, gp);
        }
    };
    auto issueB = [&](int kc, int st) {
#pragma unroll
        for (int i = 0; i < 2; ++i) {
            int tt = i * 512 + tid;
            int row = (tt >> 3) & 127;
            int seg = tt & 7;
            const __half* gp = Wp + (size_t)row * Hsz + kc * 64 + seg * 8;
            uint32_t da = sbase + SM_B_OFF + st * 16384 + row * 128 +
                          ((seg ^ (row & 7)) << 4);
            cp_async16(da, gp);
        }
    };

    // prologue: stages 0 and 1 in flight as separate groups
    issueB(0, 0); issueA(0, 0); cp_commit();
    issueB(1, 1); issueA(1, 1); cp_commit();
    cp_wait1();          // stage 0 ready (stage 1 may still be in flight)
    __syncthreads();

    int st = 0;
    for (int kc = 0; kc < 8; ++kc) {
        if (kc < 6) {
            int sn = (st + 2) % 3;
            issueB(kc + 2, sn);
            issueA(kc + 2, sn);
            cp_commit();
        }
        uint32_t aBase = sbase + SM_A_OFF + st * 32768;
        uint32_t aBaseL = aBase + 16384;
        uint32_t bBase = sbase + SM_B_OFF + st * 16384;
#pragma unroll
        for (int j = 0; j < 4; ++j) {
            uint32_t bh[4][2], af[2][4];
            load_b4(bh, bBase, j, bRow0, bRow1, kb);
            load_a2(af, aBase, j, aRow0, aRow1, kb);
            mma_2x4(acc, af, bh);          // Ah*Bh
            load_a2(af, aBaseL, j, aRow0, aRow1, kb);
            mma_2x4(acc, af, bh);          // Al*Bh
        }
        if (kc < 7) {
            if (kc < 6) cp_wait1();   // next stage ready; newest (kc+2) may fly
            else cp_wait0();          // last copy must fully land
            __syncthreads();
        }
        st = (st + 1) % 3;
    }

    // epilogue: bias + lrelu, split to fp16 hi/lo, store
#pragma unroll
    for (int mi = 0; mi < 2; ++mi)
#pragma unroll
        for (int half = 0; half < 2; ++half) {
            int r = rbase + m0 + mi * 16 + (lane >> 2) + half * 8;
            if (r < row_hi) {
#pragma unroll
                for (int nj = 0; nj < 4; ++nj) {
                    int cl = n0w + nj * 8 + (lane & 3) * 2;
                    float v0 = lrelu(acc[mi][nj][half * 2 + 0] + sbias[cl]);
                    float v1 = lrelu(acc[mi][nj][half * 2 + 1] + sbias[cl + 1]);
                    __half h0 = __float2half_rn(v0), h1 = __float2half_rn(v1);
                    float l0 = v0 - __half2float(h0), l1 = v1 - __half2float(h1);
                    size_t o = (size_t)r * Hsz + cb0 + cl;
                    *(uint32_t*)(&oH[o]) = (uint32_t)__half_as_ushort(h0) |
                                           ((uint32_t)__half_as_ushort(h1) << 16);
                    *(uint32_t*)(&oL[o]) = hpack(l0, l1);
                }
            }
        }
}

// ---------------- final layer: 128x64 tile, 256 threads, scatter to out[perm] ----------
// smem: [0,256) bias; A @1024: [2][2][16384]=65536; B @66560: [8192]. total 74752.
#define FSM_A_OFF 1024
#define FSM_B_OFF 66560
#define SMEM_FIN 74752

__global__ __launch_bounds__(256) void k_fin(int src, const float* __restrict__ bias,
                                             float* __restrict__ out) {
    extern __shared__ char sm[];
    int tid = threadIdx.x;
    int t = blockIdx.y;
    if (t >= g_ntiles) return;
    int d = g_tile_d[t];
    int rbase = g_tile_r0[t];
    int row_hi = g_dstart[d + 1];
    int rclamp = row_hi - 1;

    const __half* aH = g_aH[src];
    const __half* aL = g_aL[src];
    const __half* Wp = g_fW + (size_t)d * Ssz * Hsz;
    const float* bp = bias + (size_t)d * Ssz;

    float* sbias = (float*)sm;
    if (tid < 64) sbias[tid] = bp[tid];
    uint32_t sbase = smem_u32(sm);

    int wid = tid >> 5, lane = tid & 31;
    int wr = wid >> 2, wc = wid & 3;
    int m0 = wr * 64, n0w = wc * 16;
    int kb = lane >> 4;

    float acc[4][2][4];
#pragma unroll
    for (int i = 0; i < 4; ++i)
#pragma unroll
        for (int j = 0; j < 2; ++j)
#pragma unroll
            for (int k = 0; k < 4; ++k) acc[i][j][k] = 0.0f;

    auto issueA = [&](int kc, int st) {
#pragma unroll
        for (int i = 0; i < 8; ++i) {
            int tt = i * 256 + tid;
            int plane = tt >> 10;
            int row = (tt >> 3) & 127;
            int seg = tt & 7;
            int rg = rbase + row; if (rg > rclamp) rg = rclamp;
            const __half* gp = (plane ? aL : aH) + (size_t)rg * Hsz + kc * 64 + seg * 8;
            uint32_t da = sbase + FSM_A_OFF + st * 32768 + plane * 16384 + row * 128 +
                          ((seg ^ (row & 7)) << 4);
            cp_async16(da, gp);
        }
    };
    auto issueB = [&](int kc) {
#pragma unroll
        for (int i = 0; i < 2; ++i) {
            int tt = i * 256 + tid;
            int row = (tt >> 3) & 63;
            int seg = tt & 7;
            const __half* gp = Wp + (size_t)row * Hsz + kc * 64 + seg * 8;
            uint32_t da = sbase + FSM_B_OFF + row * 128 + ((seg ^ (row & 7)) << 4);
            cp_async16(da, gp);
        }
    };

    issueB(0);
    issueA(0, 0);
    cp_commit();
    cp_wait0();
    __syncthreads();

    for (int kc = 0; kc < 8; ++kc) {
        int st = kc & 1;
        if (kc < 7) {
            issueA(kc + 1, st ^ 1);
            cp_commit();
        }
        uint32_t aBase = sbase + FSM_A_OFF + st * 32768;
        uint32_t aBaseL = aBase + 16384;
        uint32_t bBase = sbase + FSM_B_OFF;
#pragma unroll
        for (int j = 0; j < 4; ++j) {
            uint32_t bh[2][2], ah[4][4], al[4][4];
            {
                int lrow = n0w + (lane & 15);
                uint32_t addr = bBase + lrow * 128 + (((j * 2 + kb) ^ (lrow & 7)) << 4);
                uint32_t r0, r1, r2, r3;
                ldm4(r0, r1, r2, r3, addr);
                bh[0][0] = r0; bh[0][1] = r2; bh[1][0] = r1; bh[1][1] = r3;
            }
#pragma unroll
            for (int ti = 0; ti < 4; ++ti) {
                int lrow = m0 + ti * 16 + (lane & 15);
                uint32_t addr = aBase + lrow * 128 + (((j * 2 + kb) ^ (lrow & 7)) << 4);
                ldm4(ah[ti][0], ah[ti][1], ah[ti][2], ah[ti][3], addr);
            }
#pragma unroll
            for (int mi = 0; mi < 4; ++mi)
#pragma unroll
                for (int nj = 0; nj < 2; ++nj)
                    mma16816(acc[mi][nj], ah[mi], bh[nj][0], bh[nj][1]);
#pragma unroll
            for (int ti = 0; ti < 4; ++ti) {
                int lrow = m0 + ti * 16 + (lane & 15);
                uint32_t addr = aBaseL + lrow * 128 + (((j * 2 + kb) ^ (lrow & 7)) << 4);
                ldm4(al[ti][0], al[ti][1], al[ti][2], al[ti][3], addr);
            }
#pragma unroll
            for (int mi = 0; mi < 4; ++mi)
#pragma unroll
                for (int nj = 0; nj < 2; ++nj)
                    mma16816(acc[mi][nj], al[mi], bh[nj][0], bh[nj][1]);
        }
        __syncthreads();
        if (kc < 7) {
            issueB(kc + 1);
            cp_commit();
            cp_wait0();
            __syncthreads();
        }
    }

#pragma unroll
    for (int mi = 0; mi < 4; ++mi)
#pragma unroll
        for (int half = 0; half < 2; ++half) {
            int r = rbase + m0 + mi * 16 + (lane >> 2) + half * 8;
            if (r < row_hi) {
                int ob = g_perm[r];
#pragma unroll
                for (int nj = 0; nj < 2; ++nj) {
                    int cl = n0w + nj * 8 + (lane & 3) * 2;
                    float2 o;
                    o.x = acc[mi][nj][half * 2 + 0] + sbias[cl];
                    o.y = acc[mi][nj][half * 2 + 1] + sbias[cl + 1];
                    *(float2*)(out + (size_t)ob * Ssz + cl) = o;
                }
            }
        }
}

// ---------------- launch ----------------
extern "C" void kernel_launch(void* const* d_in, const int* in_sizes, int n_in,
                              void* d_out, int out_size) {
    const float* z   = (const float*)d_in[0];
    const int*   y   = (const int*)d_in[1];
    const float* tW0 = (const float*)d_in[2];
    const float* tb0 = (const float*)d_in[3];
    const float* tW1 = (const float*)d_in[4];
    const float* tb1 = (const float*)d_in[5];
    const float* tW2 = (const float*)d_in[6];
    const float* tb2 = (const float*)d_in[7];
    const float* tW3 = (const float*)d_in[8];
    const float* tb3 = (const float*)d_in[9];
    const float* hW0 = (const float*)d_in[10];
    const float* hb0 = (const float*)d_in[11];
    const float* hW1 = (const float*)d_in[12];
    const float* hb1 = (const float*)d_in[13];
    const float* hW2 = (const float*)d_in[14];
    const float* hb2 = (const float*)d_in[15];
    const float* hW3 = (const float*)d_in[16];
    const float* hb3 = (const float*)d_in[17];
    float* out = (float*)d_out;

    cudaFuncSetAttribute(k_hmma, cudaFuncAttributeMaxDynamicSharedMemorySize, SMEM_MAIN);
    cudaFuncSetAttribute(k_fin, cudaFuncAttributeMaxDynamicSharedMemorySize, SMEM_FIN);

    k_bucket<<<1, 1024>>>(y);                                         // 0
    k_prep_all<<<13568, dim3(32, 8)>>>(tW1, tW2, tW3, hW0, hW1, hW2, hW3); // 1
    k_layer0<<<Bsz / 32, 256>>>(z, tW0, tb0);                         // 2

    // trunk: buf0 -> buf1 -> buf0 -> buf1
    k_hmma<<<dim3(4, 64), 512, SMEM_MAIN>>>(0, 1, 0, 0, tb1, 0, 0);   // 3 <- profiled
    k_hmma<<<dim3(4, 64), 512, SMEM_MAIN>>>(1, 0, 0, 1, tb2, 0, 0);
    k_hmma<<<dim3(4, 64), 512, SMEM_MAIN>>>(0, 1, 0, 2, tb3, 0, 0);
    // heads: buf1 -> buf0 -> buf1 -> buf0
    k_hmma<<<dim3(4, 80), 512, SMEM_MAIN>>>(1, 0, 1, 0, hb0, Hsz, 1);
    k_hmma<<<dim3(4, 80), 512, SMEM_MAIN>>>(0, 1, 1, 1, hb1, Hsz, 1);
    k_hmma<<<dim3(4, 80), 512, SMEM_MAIN>>>(1, 0, 1, 2, hb2, Hsz, 1);
    // final: buf0 -> out
    k_fin<<<dim3(1, 80), 256, SMEM_FIN>>>(0, hb3, out);
}

// round 17
// speedup vs baseline: 1.0411x; 1.0411x over previous
#include <cuda_runtime.h>
#include <cuda_fp16.h>
#include <cstdint>

#define Bsz 8192
#define Lsz 16
#define Hsz 512
#define Ssz 64
#define Dsz 16

// ---------------- device scratch ----------------
__device__ int g_perm[Bsz];
__device__ int g_dstart[Dsz + 1];
__device__ int g_tile_d[96];     // 128-row tiles (head hidden layers)
__device__ int g_tile_r0[96];
__device__ int g_ntiles;
__device__ int g_t64_d[160];     // 64-row tiles (final layer)
__device__ int g_t64_r0[160];
__device__ int g_n64;

// activations: fp16 hi/lo planes, ping-pong buffers
__device__ __half g_aH[2][Bsz * Hsz];
__device__ __half g_aL[2][Bsz * Hsz];

// weights: single fp16 plane, transposed to [N, K] K-major
__device__ __half g_tW[3][Hsz * Hsz];
__device__ __half g_hW[3][Dsz * Hsz * Hsz];
__device__ __half g_fW[Dsz * Ssz * Hsz];

__device__ __forceinline__ float lrelu(float x) { return x >= 0.0f ? x : 0.2f * x; }

__device__ __forceinline__ uint32_t smem_u32(const void* p) {
    uint32_t a;
    asm("{ .reg .u64 t; cvta.to.shared.u64 t, %1; cvt.u32.u64 %0, t; }" : "=r"(a) : "l"(p));
    return a;
}

__device__ __forceinline__ void cp_async16(uint32_t daddr, const void* gp) {
    asm volatile("cp.async.cg.shared.global [%0], [%1], 16;" :: "r"(daddr), "l"(gp));
}
__device__ __forceinline__ void cp_commit() {
    asm volatile("cp.async.commit_group;" ::: "memory");
}
__device__ __forceinline__ void cp_wait0() {
    asm volatile("cp.async.wait_group 0;" ::: "memory");
}

__device__ __forceinline__ void ldm4(uint32_t& r0, uint32_t& r1, uint32_t& r2, uint32_t& r3,
                                     uint32_t addr) {
    asm volatile("ldmatrix.sync.aligned.m8n8.x4.shared.b16 {%0,%1,%2,%3}, [%4];"
                 : "=r"(r0), "=r"(r1), "=r"(r2), "=r"(r3) : "r"(addr));
}

__device__ __forceinline__ void mma16816(float (&c)[4], const uint32_t (&a)[4],
                                         uint32_t b0, uint32_t b1) {
    asm("mma.sync.aligned.m16n8k16.row.col.f32.f16.f16.f32 "
        "{%0,%1,%2,%3}, {%4,%5,%6,%7}, {%8,%9}, {%0,%1,%2,%3};"
        : "+f"(c[0]), "+f"(c[1]), "+f"(c[2]), "+f"(c[3])
        : "r"(a[0]), "r"(a[1]), "r"(a[2]), "r"(a[3]), "r"(b0), "r"(b1));
}

__device__ __forceinline__ uint32_t hpack(float a, float b) {
    __half ha = __float2half_rn(a), hb = __float2half_rn(b);
    return (uint32_t)__half_as_ushort(ha) | ((uint32_t)__half_as_ushort(hb) << 16);
}

// ---------------- fused bucketing ----------------
__global__ __launch_bounds__(1024) void k_bucket(const int* __restrict__ y) {
    __shared__ int cnt[Dsz];
    __shared__ int off[Dsz];
    int tid = threadIdx.x;
    if (tid < Dsz) cnt[tid] = 0;
    __syncthreads();
    for (int i = tid; i < Bsz; i += 1024) atomicAdd(&cnt[y[i]], 1);
    __syncthreads();
    if (tid == 0) {
        int s = 0;
        int nt = 0, n64 = 0;
        for (int d = 0; d < Dsz; ++d) {
            g_dstart[d] = s;
            off[d] = s;
            for (int r = s; r < s + cnt[d]; r += 128) {
                g_tile_d[nt] = d;
                g_tile_r0[nt] = r;
                nt++;
            }
            for (int r = s; r < s + cnt[d]; r += 64) {
                g_t64_d[n64] = d;
                g_t64_r0[n64] = r;
                n64++;
            }
            s += cnt[d];
        }
        g_dstart[Dsz] = s;
        g_ntiles = nt;
        g_n64 = n64;
    }
    __syncthreads();
    for (int i = tid; i < Bsz; i += 1024) {
        int p = atomicAdd(&off[y[i]], 1);
        g_perm[p] = i;
    }
}

// ---------------- weight prep: fp32 [K,N] -> fp16 [N,K] ----------------
__global__ void k_prep_all(const float* __restrict__ tW1, const float* __restrict__ tW2,
                           const float* __restrict__ tW3, const float* __restrict__ hW0,
                           const float* __restrict__ hW1, const float* __restrict__ hW2,
                           const float* __restrict__ hW3) {
    __shared__ float t[32][33];
    int gid = blockIdx.x;
    const float* W;
    __half* Th;
    int N, bx, by;
    if (gid < 768) {
        int l = gid >> 8, rem = gid & 255;
        bx = rem & 15; by = rem >> 4;
        W = (l == 0) ? tW1 : (l == 1) ? tW2 : tW3;
        N = Hsz;
        Th = g_tW[l];
    } else if (gid < 13056) {
        int q = gid - 768;
        int l = q / 4096;
        int q2 = q & 4095;
        int z = q2 >> 8, rem = q2 & 255;
        bx = rem & 15; by = rem >> 4;
        const float* base = (l == 0) ? hW0 : (l == 1) ? hW1 : hW2;
        W = base + (size_t)z * Hsz * Hsz;
        N = Hsz;
        Th = g_hW[l] + (size_t)z * Hsz * Hsz;
    } else {
        int q = gid - 13056;
        int z = q >> 5, rem = q & 31;
        bx = rem & 1; by = rem >> 1;
        W = hW3 + (size_t)z * Hsz * Ssz;
        N = Ssz;
        Th = g_fW + (size_t)z * Ssz * Hsz;
    }
    int n0 = bx * 32, k0 = by * 32;
    int tx = threadIdx.x, ty = threadIdx.y;
#pragma unroll
    for (int i = 0; i < 4; ++i)
        t[ty + 8 * i][tx] = W[(size_t)(k0 + ty + 8 * i) * N + n0 + tx];
    __syncthreads();
#pragma unroll
    for (int i = 0; i < 4; ++i) {
        float v = t[tx][ty + 8 * i];
        int n = n0 + ty + 8 * i, k = k0 + tx;
        Th[(size_t)n * Hsz + k] = __float2half_rn(v);
    }
}

// ---------------- layer 0 ----------------
__global__ __launch_bounds__(256) void k_layer0(const float* __restrict__ z,
                                                const float* __restrict__ W,
                                                const float* __restrict__ bias) {
    __shared__ float sW[Lsz * Hsz];
    __shared__ float sb[Hsz];
    int tid = threadIdx.x;
    for (int i = tid; i < Lsz * Hsz; i += 256) sW[i] = W[i];
    for (int i = tid; i < Hsz; i += 256) sb[i] = bias[i];
    __syncthreads();

    int w = tid >> 5, lane = tid & 31;
    for (int q = 0; q < 4; ++q) {
        int p = blockIdx.x * 32 + w * 4 + q;
        int b = g_perm[p];
        float zr[Lsz];
#pragma unroll
        for (int k = 0; k < Lsz; ++k) zr[k] = __ldg(&z[b * Lsz + k]);
#pragma unroll
        for (int it = 0; it < 8; ++it) {
            int c = it * 64 + lane * 2;
            float a0 = sb[c], a1 = sb[c + 1];
#pragma unroll
            for (int k = 0; k < Lsz; ++k) {
                a0 = fmaf(zr[k], sW[k * Hsz + c], a0);
                a1 = fmaf(zr[k], sW[k * Hsz + c + 1], a1);
            }
            a0 = lrelu(a0); a1 = lrelu(a1);
            __half h0 = __float2half_rn(a0), h1 = __float2half_rn(a1);
            float l0 = a0 - __half2float(h0), l1 = a1 - __half2float(h1);
            size_t o = (size_t)p * Hsz + c;
            *(uint32_t*)(&g_aH[0][o]) = (uint32_t)__half_as_ushort(h0) |
                                        ((uint32_t)__half_as_ushort(h1) << 16);
            *(uint32_t*)(&g_aL[0][o]) = hpack(l0, l1);
        }
    }
}

// ---------------- fragment-load helpers ----------------
__device__ __forceinline__ void load_b4(uint32_t (&dst)[4][2], uint32_t base, int jj,
                                        int row0, int row1, int kb) {
    uint32_t r0, r1, r2, r3;
    uint32_t a0 = base + row0 * 128 + (((jj * 2 + kb) ^ (row0 & 7)) << 4);
    ldm4(r0, r1, r2, r3, a0);
    dst[0][0] = r0; dst[0][1] = r2; dst[1][0] = r1; dst[1][1] = r3;
    uint32_t a1 = base + row1 * 128 + (((jj * 2 + kb) ^ (row1 & 7)) << 4);
    ldm4(r0, r1, r2, r3, a1);
    dst[2][0] = r0; dst[2][1] = r2; dst[3][0] = r1; dst[3][1] = r3;
}

__device__ __forceinline__ void load_a2(uint32_t (&dst)[2][4], uint32_t base, int jj,
                                        int row0, int row1, int kb) {
    uint32_t a0 = base + row0 * 128 + (((jj * 2 + kb) ^ (row0 & 7)) << 4);
    ldm4(dst[0][0], dst[0][1], dst[0][2], dst[0][3], a0);
    uint32_t a1 = base + row1 * 128 + (((jj * 2 + kb) ^ (row1 & 7)) << 4);
    ldm4(dst[1][0], dst[1][1], dst[1][2], dst[1][3], a1);
}

__device__ __forceinline__ void mma_2x4(float (&acc)[2][4][4], const uint32_t (&aa)[2][4],
                                        const uint32_t (&bb)[4][2]) {
#pragma unroll
    for (int mi = 0; mi < 2; ++mi)
#pragma unroll
        for (int nj = 0; nj < 4; ++nj)
            mma16816(acc[mi][nj], aa[mi], bb[nj][0], bb[nj][1]);
}

// ---------------- HMMA GEMM: 128x128 tile, 512 threads, fp16x2, 2 CTAs/SM (R13) --------
#define SM_A_OFF 1024
#define SM_B_OFF 66560
#define SMEM_MAIN 99328

__global__ __launch_bounds__(512, 2) void k_hmma(int src, int dst, int wsel, int lidx,
                                                 const float* __restrict__ bias,
                                                 int bStride, int headMode) {
    extern __shared__ char sm[];
    int tid = threadIdx.x;
    int t = blockIdx.y;
    int d, rbase, row_hi;
    if (headMode) {
        if (t >= g_ntiles) return;
        d = g_tile_d[t]; rbase = g_tile_r0[t]; row_hi = g_dstart[d + 1];
    } else {
        d = 0; rbase = t * 128; row_hi = Bsz;
    }
    int cb0 = blockIdx.x * 128;
    int rclamp = row_hi - 1;

    const __half* aH = g_aH[src];
    const __half* aL = g_aL[src];
    __half* oH = g_aH[dst];
    __half* oL = g_aL[dst];
    const __half* Wp = (wsel == 0) ? g_tW[lidx]
                                   : (g_hW[lidx] + (size_t)d * Hsz * Hsz);
    Wp += (size_t)cb0 * Hsz;
    const float* bp = bias + (size_t)d * bStride + cb0;

    float* sbias = (float*)sm;
    if (tid < 128) sbias[tid] = bp[tid];
    uint32_t sbase = smem_u32(sm);

    int wid = tid >> 5, lane = tid & 31;
    int wr = wid >> 2, wc = wid & 3;
    int m0 = wr * 32, n0w = wc * 32;
    int kb = lane >> 4;

    int bRow0 = n0w + (lane & 15), bRow1 = n0w + 16 + (lane & 15);
    int aRow0 = m0 + (lane & 15), aRow1 = m0 + 16 + (lane & 15);

    float acc[2][4][4];
#pragma unroll
    for (int i = 0; i < 2; ++i)
#pragma unroll
        for (int j = 0; j < 4; ++j)
#pragma unroll
            for (int k = 0; k < 4; ++k) acc[i][j][k] = 0.0f;

    auto issueA = [&](int kc, int st) {
#pragma unroll
        for (int i = 0; i < 4; ++i) {
            int tt = i * 512 + tid;
            int plane = tt >> 10;
            int row = (tt >> 3) & 127;
            int seg = tt & 7;
            int rg = rbase + row; if (rg > rclamp) rg = rclamp;
            const __half* gp = (plane ? aL : aH) + (size_t)rg * Hsz + kc * 64 + seg * 8;
            uint32_t da = sbase + SM_A_OFF + st * 32768 + plane * 16384 + row * 128 +
                          ((seg ^ (row & 7)) << 4);
            cp_async16(da, gp);
        }
    };
    auto issueB = [&](int kc, int st) {
#pragma unroll
        for (int i = 0; i < 2; ++i) {
            int tt = i * 512 + tid;
            int row = (tt >> 3) & 127;
            int seg = tt & 7;
            const __half* gp = Wp + (size_t)row * Hsz + kc * 64 + seg * 8;
            uint32_t da = sbase + SM_B_OFF + st * 16384 + row * 128 +
                          ((seg ^ (row & 7)) << 4);
            cp_async16(da, gp);
        }
    };

    issueB(0, 0);
    issueA(0, 0);
    cp_commit();
    cp_wait0();
    __syncthreads();

    for (int kc = 0; kc < 8; ++kc) {
        int st = kc & 1;
        if (kc < 7) {
            issueB(kc + 1, st ^ 1);
            issueA(kc + 1, st ^ 1);
            cp_commit();
        }
        uint32_t aBase = sbase + SM_A_OFF + st * 32768;
        uint32_t aBaseL = aBase + 16384;
        uint32_t bBase = sbase + SM_B_OFF + st * 16384;
#pragma unroll
        for (int j = 0; j < 4; ++j) {
            uint32_t bh[4][2], af[2][4];
            load_b4(bh, bBase, j, bRow0, bRow1, kb);
            load_a2(af, aBase, j, aRow0, aRow1, kb);
            mma_2x4(acc, af, bh);          // Ah*Bh
            load_a2(af, aBaseL, j, aRow0, aRow1, kb);
            mma_2x4(acc, af, bh);          // Al*Bh
        }
        if (kc < 7) cp_wait0();
        __syncthreads();
    }

#pragma unroll
    for (int mi = 0; mi < 2; ++mi)
#pragma unroll
        for (int half = 0; half < 2; ++half) {
            int r = rbase + m0 + mi * 16 + (lane >> 2) + half * 8;
            if (r < row_hi) {
#pragma unroll
                for (int nj = 0; nj < 4; ++nj) {
                    int cl = n0w + nj * 8 + (lane & 3) * 2;
                    float v0 = lrelu(acc[mi][nj][half * 2 + 0] + sbias[cl]);
                    float v1 = lrelu(acc[mi][nj][half * 2 + 1] + sbias[cl + 1]);
                    __half h0 = __float2half_rn(v0), h1 = __float2half_rn(v1);
                    float l0 = v0 - __half2float(h0), l1 = v1 - __half2float(h1);
                    size_t o = (size_t)r * Hsz + cb0 + cl;
                    *(uint32_t*)(&oH[o]) = (uint32_t)__half_as_ushort(h0) |
                                           ((uint32_t)__half_as_ushort(h1) << 16);
                    *(uint32_t*)(&oL[o]) = hpack(l0, l1);
                }
            }
        }
}

// ---------------- final layer: 64x64 tiles, 256 threads, double-buffered A AND B ------
// smem: [0,256) bias; A @1024: [2 st][2 pl][8192] = 32768; B @33792: [2 st][8192] = 16384.
// total 50176.
#define FSM_A_OFF 1024
#define FSM_B_OFF 33792
#define SMEM_FIN 50176

__global__ __launch_bounds__(256) void k_fin(int src, const float* __restrict__ bias,
                                             float* __restrict__ out) {
    extern __shared__ char sm[];
    int tid = threadIdx.x;
    int t = blockIdx.y;
    if (t >= g_n64) return;
    int d = g_t64_d[t];
    int rbase = g_t64_r0[t];
    int row_hi = g_dstart[d + 1];
    int rclamp = row_hi - 1;

    const __half* aH = g_aH[src];
    const __half* aL = g_aL[src];
    const __half* Wp = g_fW + (size_t)d * Ssz * Hsz;
    const float* bp = bias + (size_t)d * Ssz;

    float* sbias = (float*)sm;
    if (tid < 64) sbias[tid] = bp[tid];
    uint32_t sbase = smem_u32(sm);

    int wid = tid >> 5, lane = tid & 31;
    int wr = wid >> 2, wc = wid & 3;   // 2 x 4 warp grid
    int m0 = wr * 32, n0w = wc * 16;   // warp tile 32 x 16
    int kb = lane >> 4;

    int aRow0 = m0 + (lane & 15), aRow1 = m0 + 16 + (lane & 15);
    int bRow = n0w + (lane & 15);

    float acc[2][2][4];
#pragma unroll
    for (int i = 0; i < 2; ++i)
#pragma unroll
        for (int j = 0; j < 2; ++j)
#pragma unroll
            for (int k = 0; k < 4; ++k) acc[i][j][k] = 0.0f;

    auto issueA = [&](int kc, int st) {
#pragma unroll
        for (int i = 0; i < 4; ++i) {
            int tt = i * 256 + tid;
            int plane = tt >> 9;
            int row = (tt >> 3) & 63;
            int seg = tt & 7;
            int rg = rbase + row; if (rg > rclamp) rg = rclamp;
            const __half* gp = (plane ? aL : aH) + (size_t)rg * Hsz + kc * 64 + seg * 8;
            uint32_t da = sbase + FSM_A_OFF + st * 16384 + plane * 8192 + row * 128 +
                          ((seg ^ (row & 7)) << 4);
            cp_async16(da, gp);
        }
    };
    auto issueB = [&](int kc, int st) {
#pragma unroll
        for (int i = 0; i < 2; ++i) {
            int tt = i * 256 + tid;
            int row = (tt >> 3) & 63;
            int seg = tt & 7;
            const __half* gp = Wp + (size_t)row * Hsz + kc * 64 + seg * 8;
            uint32_t da = sbase + FSM_B_OFF + st * 8192 + row * 128 +
                          ((seg ^ (row & 7)) << 4);
            cp_async16(da, gp);
        }
    };

    issueB(0, 0);
    issueA(0, 0);
    cp_commit();
    cp_wait0();
    __syncthreads();

    for (int kc = 0; kc < 8; ++kc) {
        int st = kc & 1;
        if (kc < 7) {
            issueB(kc + 1, st ^ 1);
            issueA(kc + 1, st ^ 1);
            cp_commit();
        }
        uint32_t aBase = sbase + FSM_A_OFF + st * 16384;
        uint32_t aBaseL = aBase + 8192;
        uint32_t bBase = sbase + FSM_B_OFF + st * 8192;
#pragma unroll
        for (int j = 0; j < 4; ++j) {
            uint32_t bh[2][2], ah[2][4], al[2][4];
            {
                uint32_t addr = bBase + bRow * 128 + (((j * 2 + kb) ^ (bRow & 7)) << 4);
                uint32_t r0, r1, r2, r3;
                ldm4(r0, r1, r2, r3, addr);
                bh[0][0] = r0; bh[0][1] = r2; bh[1][0] = r1; bh[1][1] = r3;
            }
            load_a2(ah, aBase, j, aRow0, aRow1, kb);
#pragma unroll
            for (int mi = 0; mi < 2; ++mi)
#pragma unroll
                for (int nj = 0; nj < 2; ++nj)
                    mma16816(acc[mi][nj], ah[mi], bh[nj][0], bh[nj][1]);
            load_a2(al, aBaseL, j, aRow0, aRow1, kb);
#pragma unroll
            for (int mi = 0; mi < 2; ++mi)
#pragma unroll
                for (int nj = 0; nj < 2; ++nj)
                    mma16816(acc[mi][nj], al[mi], bh[nj][0], bh[nj][1]);
        }
        if (kc < 7) cp_wait0();
        __syncthreads();
    }

#pragma unroll
    for (int mi = 0; mi < 2; ++mi)
#pragma unroll
        for (int half = 0; half < 2; ++half) {
            int r = rbase + m0 + mi * 16 + (lane >> 2) + half * 8;
            if (r < row_hi) {
                int ob = g_perm[r];
#pragma unroll
                for (int nj = 0; nj < 2; ++nj) {
                    int cl = n0w + nj * 8 + (lane & 3) * 2;
                    float2 o;
                    o.x = acc[mi][nj][half * 2 + 0] + sbias[cl];
                    o.y = acc[mi][nj][half * 2 + 1] + sbias[cl + 1];
                    *(float2*)(out + (size_t)ob * Ssz + cl) = o;
                }
            }
        }
}

// ---------------- launch (linear, single stream — capture-safe) ----------------
extern "C" void kernel_launch(void* const* d_in, const int* in_sizes, int n_in,
                              void* d_out, int out_size) {
    const float* z   = (const float*)d_in[0];
    const int*   y   = (const int*)d_in[1];
    const float* tW0 = (const float*)d_in[2];
    const float* tb0 = (const float*)d_in[3];
    const float* tW1 = (const float*)d_in[4];
    const float* tb1 = (const float*)d_in[5];
    const float* tW2 = (const float*)d_in[6];
    const float* tb2 = (const float*)d_in[7];
    const float* tW3 = (const float*)d_in[8];
    const float* tb3 = (const float*)d_in[9];
    const float* hW0 = (const float*)d_in[10];
    const float* hb0 = (const float*)d_in[11];
    const float* hW1 = (const float*)d_in[12];
    const float* hb1 = (const float*)d_in[13];
    const float* hW2 = (const float*)d_in[14];
    const float* hb2 = (const float*)d_in[15];
    const float* hW3 = (const float*)d_in[16];
    const float* hb3 = (const float*)d_in[17];
    float* out = (float*)d_out;

    cudaFuncSetAttribute(k_hmma, cudaFuncAttributeMaxDynamicSharedMemorySize, SMEM_MAIN);
    cudaFuncSetAttribute(k_fin, cudaFuncAttributeMaxDynamicSharedMemorySize, SMEM_FIN);

    k_bucket<<<1, 1024>>>(y);
    k_prep_all<<<13568, dim3(32, 8)>>>(tW1, tW2, tW3, hW0, hW1, hW2, hW3);
    k_layer0<<<Bsz / 32, 256>>>(z, tW0, tb0);

    // trunk: buf0 -> buf1 -> buf0 -> buf1
    k_hmma<<<dim3(4, 64), 512, SMEM_MAIN>>>(0, 1, 0, 0, tb1, 0, 0);
    k_hmma<<<dim3(4, 64), 512, SMEM_MAIN>>>(1, 0, 0, 1, tb2, 0, 0);
    k_hmma<<<dim3(4, 64), 512, SMEM_MAIN>>>(0, 1, 0, 2, tb3, 0, 0);
    // heads: buf1 -> buf0 -> buf1 -> buf0
    k_hmma<<<dim3(4, 80), 512, SMEM_MAIN>>>(1, 0, 1, 0, hb0, Hsz, 1);
    k_hmma<<<dim3(4, 80), 512, SMEM_MAIN>>>(0, 1, 1, 1, hb1, Hsz, 1);
    k_hmma<<<dim3(4, 80), 512, SMEM_MAIN>>>(1, 0, 1, 2, hb2, Hsz, 1);
    // final: buf0 -> out (64-row tiles, full-chip occupancy)
    k_fin<<<dim3(1, 160), 256, SMEM_FIN>>>(0, hb3, out);
}